// round 8
// baseline (speedup 1.0000x reference)
#include <cuda_runtime.h>
#include <cuda_fp16.h>
#include <cstdint>

// ---------------- device scratch (no allocations allowed) ----------------
// Transposed fp16 weights, chunk-tiled (chunk = 64 k'):
// Wt[c][h][kk], kk = nl*32 + m (nl=0..1), n = 2c + nl, original k = m*NIN + n.
__device__ __half g_wt0[256 * 1024];
__device__ __half g_wt1[256 * 4096];
__device__ __half g_wt2[256 * 4096];

__device__ __forceinline__ uint32_t smem_u32(const void* p) {
    uint32_t r;
    asm("{ .reg .u64 t; cvta.to.shared.u64 t, %1; cvt.u32.u64 %0, t; }" : "=r"(r) : "l"(p));
    return r;
}
__device__ __forceinline__ uint32_t h2u(__half2 v) { return *reinterpret_cast<uint32_t*>(&v); }
__device__ __forceinline__ void cp16(uint32_t dst, const void* src) {
    asm volatile("cp.async.cg.shared.global [%0], [%1], 16;" :: "r"(dst), "l"(src) : "memory");
}
__device__ __forceinline__ void cp_mbar_arrive(uint32_t mbar) {
    asm volatile("cp.async.mbarrier.arrive.noinc.shared.b64 [%0];" :: "r"(mbar) : "memory");
}
__device__ __forceinline__ void mbar_init(uint32_t a, uint32_t c) {
    asm volatile("mbarrier.init.shared.b64 [%0], %1;" :: "r"(a), "r"(c) : "memory");
}
__device__ __forceinline__ void mbar_arrive(uint32_t a) {
    asm volatile("mbarrier.arrive.shared.b64 _, [%0];" :: "r"(a) : "memory");
}
__device__ __forceinline__ void mbar_wait(uint32_t a, uint32_t ph) {
    asm volatile(
        "{\n\t.reg .pred P;\n"
        "W_%=:\n\t"
        "mbarrier.try_wait.parity.shared.b64 P, [%0], %1, 0x989680;\n\t"
        "@P bra.uni D_%=;\n\t"
        "bra.uni W_%=;\n"
        "D_%=:\n\t}"
        :: "r"(a), "r"(ph) : "memory");
}
__device__ __forceinline__ void ldsm4(uint32_t* r, uint32_t a) {
    asm volatile("ldmatrix.sync.aligned.m8n8.x4.shared.b16 {%0,%1,%2,%3}, [%4];"
                 : "=r"(r[0]), "=r"(r[1]), "=r"(r[2]), "=r"(r[3]) : "r"(a));
}
__device__ __forceinline__ void mma16(float* c, const uint32_t* a, const uint32_t* b) {
    asm volatile("mma.sync.aligned.m16n8k16.row.col.f32.f16.f16.f32 "
                 "{%0,%1,%2,%3},{%4,%5,%6,%7},{%8,%9},{%0,%1,%2,%3};"
                 : "+f"(c[0]), "+f"(c[1]), "+f"(c[2]), "+f"(c[3])
                 : "r"(a[0]), "r"(a[1]), "r"(a[2]), "r"(a[3]), "r"(b[0]), "r"(b[1]));
}

// ---------------- weight transpose (fp16, chunk-64 tiling, coalesced) ----------------
template <int NIN>
__global__ void __launch_bounds__(256) wtrans(const float* __restrict__ W, __half* __restrict__ Wt) {
    __shared__ __half s[64 * 256];
    const int c = blockIdx.x, t = threadIdx.x;
#pragma unroll 4
    for (int kk = 0; kk < 64; kk++) {
        int m = kk & 31, nl = kk >> 5;
        int n = 2 * c + nl;
        int k = m * NIN + n;
        s[kk * 256 + t] = __float2half_rn(W[(size_t)k * 256 + t]);
    }
    __syncthreads();
    __half* dst = Wt + (size_t)c * 16384 + (size_t)t * 64;
#pragma unroll
    for (int j = 0; j < 8; j++) {
        uint4 v;
        v.x = h2u(__halves2half2(s[(8 * j + 0) * 256 + t], s[(8 * j + 1) * 256 + t]));
        v.y = h2u(__halves2half2(s[(8 * j + 2) * 256 + t], s[(8 * j + 3) * 256 + t]));
        v.z = h2u(__halves2half2(s[(8 * j + 4) * 256 + t], s[(8 * j + 5) * 256 + t]));
        v.w = h2u(__halves2half2(s[(8 * j + 6) * 256 + t], s[(8 * j + 7) * 256 + t]));
        *reinterpret_cast<uint4*>(dst + 8 * j) = v;
    }
}

__global__ void init_out(const float* __restrict__ fcb, float* __restrict__ out) {
    out[blockIdx.x * 256 + threadIdx.x] = fcb[0];
}

// ---------------- fused 3-layer CIN: warp-specialized fp16 mma.sync ----------------
// 512 CTAs (2 batches each, all 3 layers) x 288 threads:
//   warps 0-7 = consumers (2x4 grid, warp tile 64d x 64h); warp 8 = producer.
// K-chunk 64 (2 n). Stage (48KB): A[128 x 128B] @0, B[256 x 128B] @16384. 3 stages.
// Inter-layer h lives in SMEM hbuf[2][128][64] fp32 (64KB), written by consumer
// epilogues, read by producer A-builds; ordered by the hdone mbarrier.
// full[s]: 64 arrivals (32 cp-completions + 32 A arrives). empty[s]: 256. hdone: 256.
__global__ void __launch_bounds__(288, 1)
cin_fused(const float* __restrict__ x,
          const float* __restrict__ bias0, const float* __restrict__ bias1,
          const float* __restrict__ bias2,
          const float* __restrict__ fcW, float* __restrict__ out) {
    extern __shared__ char smc[];
    const uint32_t sb0 = smem_u32(smc);
    const uint32_t sb  = (sb0 + 1023u) & ~1023u;
    char* const smb    = smc + (sb - sb0);
    const uint32_t stg0 = sb + 1024u;
    float* const hb = reinterpret_cast<float*>(smb + 1024u + 3u * 49152u);  // 64KB

    const int t = threadIdx.x, lane = t & 31, wid = t >> 5;
    const int b0 = blockIdx.x * 2;

    if (t == 0) {
#pragma unroll
        for (int s = 0; s < 3; s++) {
            mbar_init(sb + 16 * s, 64);        // full
            mbar_init(sb + 16 * s + 8, 256);   // empty
        }
        mbar_init(sb + 48, 256);               // hdone (layer boundary)
    }
    __syncthreads();

    const __half* const wts[3] = {g_wt0, g_wt1, g_wt2};
    const int ncs[3] = {16, 64, 64};

    if (t >= 256) {
        // ================= producer (warp 8) =================
        const int ptid = t - 256;              // 0..31
        float xr[4][32];
#pragma unroll
        for (int i = 0; i < 4; i++) {
            const int row = ptid + 32 * i, bb = row >> 6, d = row & 63;
            const float* xp = x + (size_t)(b0 + bb) * 2048 + d;
#pragma unroll
            for (int m = 0; m < 32; m++) xr[i][m] = xp[m * 64];
        }
        const int hh0 = ptid >> 3, jj = ptid & 7;
        int ps = 0; uint32_t pph = 1;
        for (int L = 0; L < 3; L++) {
            if (L) mbar_wait(sb + 48, (uint32_t)(L - 1) & 1u);   // hbuf ready
            const __half* wt = wts[L];
            const int NC = ncs[L];
            for (int c = 0; c < NC; c++) {
                mbar_wait(sb + 16 * ps + 8, pph);                // stage free
                const int s = ps;
                if (++ps == 3) { ps = 0; pph ^= 1u; }
                const uint32_t stg = stg0 + (uint32_t)s * 49152u;
                // B: 2048 x 16B chunks over 32 threads -> 64 cp16 each.
                const __half* ws = wt + (size_t)c * 16384;
#pragma unroll
                for (int i = 0; i < 64; i++) {
                    const int h = hh0 + 4 * i;
                    cp16(stg + 16384u + (uint32_t)h * 128u + (uint32_t)((jj ^ (h & 7)) << 4),
                         ws + (size_t)h * 64 + jj * 8);
                }
                cp_mbar_arrive(sb + 16 * s);
                // A: 4 rows per thread.
#pragma unroll
                for (int i = 0; i < 4; i++) {
                    const int row = ptid + 32 * i, bb = row >> 6, d = row & 63;
                    const uint32_t asw = (uint32_t)(row & 7);
                    char* ab = smb + (stg - sb) + (uint32_t)row * 128u;
#pragma unroll
                    for (int nl = 0; nl < 2; nl++) {
                        const int n = 2 * c + nl;
                        const float hv = (L == 0)
                            ? __ldg(x + (size_t)(b0 + bb) * 2048 + (size_t)n * 64 + d)
                            : hb[(size_t)(bb * 128 + n) * 64 + d];
#pragma unroll
                        for (int u = 0; u < 4; u++) {
                            uint4 v;
                            v.x = h2u(__floats2half2_rn(xr[i][8*u+0]*hv, xr[i][8*u+1]*hv));
                            v.y = h2u(__floats2half2_rn(xr[i][8*u+2]*hv, xr[i][8*u+3]*hv));
                            v.z = h2u(__floats2half2_rn(xr[i][8*u+4]*hv, xr[i][8*u+5]*hv));
                            v.w = h2u(__floats2half2_rn(xr[i][8*u+6]*hv, xr[i][8*u+7]*hv));
                            const int j = nl * 4 + u;
                            *reinterpret_cast<uint4*>(ab + ((((uint32_t)j) ^ asw) << 4)) = v;
                        }
                    }
                }
                mbar_arrive(sb + 16 * s);       // A ready (release)
            }
        }
        return;
    }

    // ================= consumers (warps 0-7) =================
    const int mg = wid >> 2, ng = wid & 3;
    const int arow = mg * 64 + (lane & 15);
    const int brow = ng * 64 + ((lane >> 4) << 3) + (lane & 7);
    const uint32_t axor = (uint32_t)(arow & 7);
    const uint32_t bxor = (uint32_t)(brow & 7);
    const uint32_t aof = (uint32_t)arow * 128u;
    const uint32_t bof = 16384u + (uint32_t)brow * 128u;
    const uint32_t acs = (uint32_t)(lane >> 4);
    const uint32_t bcs = (uint32_t)((lane >> 3) & 1);
    const int b = b0 + mg;
    const int dq = lane >> 2, hq = (lane & 3) * 2;

    int cs = 0; uint32_t cph = 0;
    for (int L = 0; L < 3; L++) {
        const int NC = ncs[L];
        const float* bias = (L == 0) ? bias0 : (L == 1) ? bias1 : bias2;
        const int fcoff = (L == 0) ? 0 : (L == 1) ? 128 : 256;

        float acc[4][8][4];
#pragma unroll
        for (int i = 0; i < 4; i++)
#pragma unroll
            for (int j = 0; j < 8; j++)
#pragma unroll
                for (int q = 0; q < 4; q++) acc[i][j][q] = 0.0f;

        for (int c = 0; c < NC; c++) {
            mbar_wait(sb + 16 * cs, cph);       // stage full
            const int s = cs;
            if (++cs == 3) { cs = 0; cph ^= 1u; }
            const uint32_t stg = stg0 + (uint32_t)s * 49152u;
#pragma unroll
            for (int ks = 0; ks < 4; ks++) {
                uint32_t af[4][4], bf[4][4];
#pragma unroll
                for (int mt = 0; mt < 4; mt++)
                    ldsm4(af[mt], stg + aof + (uint32_t)(mt * 16 * 128) +
                                  ((((uint32_t)(2 * ks) + acs) ^ axor) << 4));
#pragma unroll
                for (int np = 0; np < 4; np++)
                    ldsm4(bf[np], stg + bof + (uint32_t)(np * 16 * 128) +
                                  ((((uint32_t)(2 * ks) + bcs) ^ bxor) << 4));
#pragma unroll
                for (int mt = 0; mt < 4; mt++)
#pragma unroll
                    for (int nt = 0; nt < 8; nt++)
                        mma16(acc[mt][nt], af[mt], &bf[nt >> 1][(nt & 1) * 2]);
            }
            mbar_arrive(sb + 16 * s + 8);       // stage consumed
        }

        // ---- epilogue ----
        if (L == 2 || ng < 2) {                 // fused fc dot
            float p = 0.0f;
#pragma unroll
            for (int nt = 0; nt < 8; nt++) {
                const int h = ng * 64 + nt * 8 + hq;
                const float bv0 = __ldg(bias + h), bv1 = __ldg(bias + h + 1);
                const float w0 = __ldg(fcW + fcoff + h), w1 = __ldg(fcW + fcoff + h + 1);
                float s0 = 0.0f, s1 = 0.0f;
#pragma unroll
                for (int mt = 0; mt < 4; mt++) {
                    s0 += fmaxf(acc[mt][nt][0] + bv0, 0.f) + fmaxf(acc[mt][nt][2] + bv0, 0.f);
                    s1 += fmaxf(acc[mt][nt][1] + bv1, 0.f) + fmaxf(acc[mt][nt][3] + bv1, 0.f);
                }
                p += s0 * w0 + s1 * w1;
            }
#pragma unroll
            for (int o = 16; o > 0; o >>= 1) p += __shfl_xor_sync(0xFFFFFFFFu, p, o);
            if (lane == 0) atomicAdd(out + b, p);
        }
        if (L < 2 && ng >= 2) {                 // h (next-layer input) -> SMEM hbuf
            float* yo = hb + (size_t)mg * 8192;
#pragma unroll
            for (int mt = 0; mt < 4; mt++) {
                const int d = mt * 16 + dq;
#pragma unroll
                for (int nt = 0; nt < 8; nt++) {
                    const int h = ng * 64 + nt * 8 + hq;
                    const float bv0 = __ldg(bias + h), bv1 = __ldg(bias + h + 1);
                    const int n = h - 128;
                    yo[(size_t)n * 64 + d]           = fmaxf(acc[mt][nt][0] + bv0, 0.f);
                    yo[(size_t)(n + 1) * 64 + d]     = fmaxf(acc[mt][nt][1] + bv1, 0.f);
                    yo[(size_t)n * 64 + d + 8]       = fmaxf(acc[mt][nt][2] + bv0, 0.f);
                    yo[(size_t)(n + 1) * 64 + d + 8] = fmaxf(acc[mt][nt][3] + bv1, 0.f);
                }
            }
        }
        if (L < 2) mbar_arrive(sb + 48);        // hbuf ready for producer (release)
    }
}

extern "C" void kernel_launch(void* const* d_in, const int* in_sizes, int n_in,
                              void* d_out, int out_size) {
    const float* x   = (const float*)d_in[0];
    const float* W0  = (const float*)d_in[1];
    const float* b0  = (const float*)d_in[2];
    const float* W1  = (const float*)d_in[3];
    const float* b1  = (const float*)d_in[4];
    const float* W2  = (const float*)d_in[5];
    const float* b2  = (const float*)d_in[6];
    const float* fcW = (const float*)d_in[7];
    const float* fcb = (const float*)d_in[8];
    float* out = (float*)d_out;

    // pad + mbar header + 3 stages + 64KB hbuf
    constexpr int SMEMSZ = 1024 + 1024 + 3 * 49152 + 65536;
    cudaFuncSetAttribute(cin_fused, cudaFuncAttributeMaxDynamicSharedMemorySize, SMEMSZ);

    __half *wt0p, *wt1p, *wt2p;
    cudaGetSymbolAddress((void**)&wt0p, g_wt0);
    cudaGetSymbolAddress((void**)&wt1p, g_wt1);
    cudaGetSymbolAddress((void**)&wt2p, g_wt2);

    wtrans<32>  <<<16, 256>>>(W0, wt0p);
    wtrans<128> <<<64, 256>>>(W1, wt1p);
    wtrans<128> <<<64, 256>>>(W2, wt2p);
    init_out<<<4, 256>>>(fcb, out);

    cin_fused<<<512, 288, SMEMSZ>>>(x, b0, b1, b2, fcW, out);
}

// round 9
// speedup vs baseline: 1.2396x; 1.2396x over previous
#include <cuda_runtime.h>
#include <cuda_fp16.h>
#include <cstdint>

// ---------------- device scratch (no allocations allowed) ----------------
// Transposed fp16 weights, chunk-tiled (chunk = 64 k'):
// Wt[c][h][kk], kk = nl*32 + m (nl=0..1), n = 2c + nl, original k = m*NIN + n.
__device__ __half g_wt0[256 * 1024];
__device__ __half g_wt1[256 * 4096];
__device__ __half g_wt2[256 * 4096];

__device__ __forceinline__ uint32_t smem_u32(const void* p) {
    uint32_t r;
    asm("{ .reg .u64 t; cvta.to.shared.u64 t, %1; cvt.u32.u64 %0, t; }" : "=r"(r) : "l"(p));
    return r;
}
__device__ __forceinline__ uint32_t h2u(__half2 v) { return *reinterpret_cast<uint32_t*>(&v); }
__device__ __forceinline__ void cp16(uint32_t dst, const void* src) {
    asm volatile("cp.async.cg.shared.global [%0], [%1], 16;" :: "r"(dst), "l"(src) : "memory");
}
__device__ __forceinline__ void cp_mbar_arrive(uint32_t mbar) {
    asm volatile("cp.async.mbarrier.arrive.noinc.shared.b64 [%0];" :: "r"(mbar) : "memory");
}
__device__ __forceinline__ void mbar_init(uint32_t a, uint32_t c) {
    asm volatile("mbarrier.init.shared.b64 [%0], %1;" :: "r"(a), "r"(c) : "memory");
}
__device__ __forceinline__ void mbar_arrive(uint32_t a) {
    asm volatile("mbarrier.arrive.shared.b64 _, [%0];" :: "r"(a) : "memory");
}
__device__ __forceinline__ void mbar_wait(uint32_t a, uint32_t ph) {
    asm volatile(
        "{\n\t.reg .pred P;\n"
        "W_%=:\n\t"
        "mbarrier.try_wait.parity.shared.b64 P, [%0], %1, 0x989680;\n\t"
        "@P bra.uni D_%=;\n\t"
        "bra.uni W_%=;\n"
        "D_%=:\n\t}"
        :: "r"(a), "r"(ph) : "memory");
}
__device__ __forceinline__ void ldsm4(uint32_t* r, uint32_t a) {
    asm volatile("ldmatrix.sync.aligned.m8n8.x4.shared.b16 {%0,%1,%2,%3}, [%4];"
                 : "=r"(r[0]), "=r"(r[1]), "=r"(r[2]), "=r"(r[3]) : "r"(a));
}
__device__ __forceinline__ void mma16(float* c, const uint32_t* a, const uint32_t* b) {
    asm volatile("mma.sync.aligned.m16n8k16.row.col.f32.f16.f16.f32 "
                 "{%0,%1,%2,%3},{%4,%5,%6,%7},{%8,%9},{%0,%1,%2,%3};"
                 : "+f"(c[0]), "+f"(c[1]), "+f"(c[2]), "+f"(c[3])
                 : "r"(a[0]), "r"(a[1]), "r"(a[2]), "r"(a[3]), "r"(b[0]), "r"(b[1]));
}

// ---------------- weight transpose (fp16, chunk-64 tiling, coalesced) ----------------
template <int NIN>
__global__ void __launch_bounds__(256) wtrans(const float* __restrict__ W, __half* __restrict__ Wt) {
    __shared__ __half s[64 * 256];
    const int c = blockIdx.x, t = threadIdx.x;
#pragma unroll 4
    for (int kk = 0; kk < 64; kk++) {
        int m = kk & 31, nl = kk >> 5;
        int n = 2 * c + nl;
        int k = m * NIN + n;
        s[kk * 256 + t] = __float2half_rn(W[(size_t)k * 256 + t]);
    }
    __syncthreads();
    __half* dst = Wt + (size_t)c * 16384 + (size_t)t * 64;
#pragma unroll
    for (int j = 0; j < 8; j++) {
        uint4 v;
        v.x = h2u(__halves2half2(s[(8 * j + 0) * 256 + t], s[(8 * j + 1) * 256 + t]));
        v.y = h2u(__halves2half2(s[(8 * j + 2) * 256 + t], s[(8 * j + 3) * 256 + t]));
        v.z = h2u(__halves2half2(s[(8 * j + 4) * 256 + t], s[(8 * j + 5) * 256 + t]));
        v.w = h2u(__halves2half2(s[(8 * j + 6) * 256 + t], s[(8 * j + 7) * 256 + t]));
        *reinterpret_cast<uint4*>(dst + 8 * j) = v;
    }
}

__global__ void init_out(const float* __restrict__ fcb, float* __restrict__ out) {
    out[blockIdx.x * 256 + threadIdx.x] = fcb[0];
}

// ---------------- fused 3-layer CIN: warp-specialized fp16 mma.sync ----------------
// 512 CTAs (2 batches each, all 3 layers) x 320 threads:
//   warps 0-7 = consumers (2x4 grid, warp tile 64d x 64h); warps 8-9 = producers.
// K-chunk 64 (2 n). Stage (48KB): A[128 x 128B] @0, B[256 x 128B] @16384. 3 stages.
// Inter-layer h in SMEM hbuf[2][128][64] fp32 (64KB), written by consumer epilogues,
// read by producer A-builds; ordered by the hdone mbarrier (256 arrivals).
// full[s]: 128 arrivals (64 cp-completions + 64 A arrives). empty[s]: 256.
// At layer boundaries the producer issues next-layer B cp.async BEFORE waiting
// hdone (B is hbuf-independent), hiding stage refill behind consumer epilogues.
__global__ void __launch_bounds__(320, 1)
cin_fused(const float* __restrict__ x,
          const float* __restrict__ bias0, const float* __restrict__ bias1,
          const float* __restrict__ bias2,
          const float* __restrict__ fcW, float* __restrict__ out) {
    extern __shared__ char smc[];
    const uint32_t sb0 = smem_u32(smc);
    const uint32_t sb  = (sb0 + 1023u) & ~1023u;
    char* const smb    = smc + (sb - sb0);
    const uint32_t stg0 = sb + 1024u;
    float* const hb = reinterpret_cast<float*>(smb + 1024u + 3u * 49152u);  // 64KB

    const int t = threadIdx.x, lane = t & 31, wid = t >> 5;
    const int b0 = blockIdx.x * 2;

    if (t == 0) {
#pragma unroll
        for (int s = 0; s < 3; s++) {
            mbar_init(sb + 16 * s, 128);       // full
            mbar_init(sb + 16 * s + 8, 256);   // empty
        }
        mbar_init(sb + 48, 256);               // hdone (layer boundary)
    }
    __syncthreads();

    const int ncs[3] = {16, 64, 64};

    if (t >= 256) {
        // ================= producers (warps 8-9) =================
        const int ptid = t - 256;              // 0..63
        float xr0[32], xr1[32];
        {
            const float* xp0 = x + (size_t)b0 * 2048 + ptid;
            const float* xp1 = x + (size_t)(b0 + 1) * 2048 + ptid;
#pragma unroll
            for (int m = 0; m < 32; m++) { xr0[m] = xp0[m * 64]; xr1[m] = xp1[m * 64]; }
        }
        int ps = 0; uint32_t pph = 1;
        for (int L = 0; L < 3; L++) {
            const __half* wt = (L == 0) ? g_wt0 : (L == 1) ? g_wt1 : g_wt2;
            const int NC = ncs[L];
            for (int c = 0; c < NC; c++) {
                mbar_wait(sb + 16 * ps + 8, pph);                // stage free
                const int s = ps;
                if (++ps == 3) { ps = 0; pph ^= 1u; }
                const uint32_t stg = stg0 + (uint32_t)s * 49152u;
                // B: 2048 x 16B chunks over 64 threads -> 32 cp16 each.
                const __half* ws = wt + (size_t)c * 16384;
#pragma unroll
                for (int i = 0; i < 32; i++) {
                    const int p = ptid + i * 64;
                    const int h = p >> 3, j = p & 7;
                    cp16(stg + 16384u + (uint32_t)h * 128u + (uint32_t)((j ^ (h & 7)) << 4),
                         ws + (size_t)h * 64 + j * 8);
                }
                cp_mbar_arrive(sb + 16 * s);
                // hbuf dependency only bites on the first chunk of L1/L2 —
                // after B for this stage is already in flight.
                if (L > 0 && c == 0) mbar_wait(sb + 48, (uint32_t)(L - 1) & 1u);
                // A: rows ptid (batch b0) and ptid+64 (batch b0+1).
#pragma unroll
                for (int r2 = 0; r2 < 2; r2++) {
                    const int row = ptid + r2 * 64;
                    const float* xr = r2 ? xr1 : xr0;
                    const uint32_t asw = (uint32_t)(row & 7);
                    char* ab = smb + (stg - sb) + (uint32_t)row * 128u;
#pragma unroll
                    for (int nl = 0; nl < 2; nl++) {
                        const int n = 2 * c + nl;
                        const float hv = (L == 0)
                            ? __ldg(x + (size_t)(b0 + r2) * 2048 + (size_t)n * 64 + ptid)
                            : hb[(size_t)(r2 * 128 + n) * 64 + ptid];
#pragma unroll
                        for (int u = 0; u < 4; u++) {
                            uint4 v;
                            v.x = h2u(__floats2half2_rn(xr[8*u+0]*hv, xr[8*u+1]*hv));
                            v.y = h2u(__floats2half2_rn(xr[8*u+2]*hv, xr[8*u+3]*hv));
                            v.z = h2u(__floats2half2_rn(xr[8*u+4]*hv, xr[8*u+5]*hv));
                            v.w = h2u(__floats2half2_rn(xr[8*u+6]*hv, xr[8*u+7]*hv));
                            const int j = nl * 4 + u;
                            *reinterpret_cast<uint4*>(ab + ((((uint32_t)j) ^ asw) << 4)) = v;
                        }
                    }
                }
                mbar_arrive(sb + 16 * s);       // A ready (release)
            }
        }
        return;
    }

    // ================= consumers (warps 0-7) =================
    const int mg = wid >> 2, ng = wid & 3;
    const int arow = mg * 64 + (lane & 15);
    const int brow = ng * 64 + ((lane >> 4) << 3) + (lane & 7);
    const uint32_t axor = (uint32_t)(arow & 7);
    const uint32_t bxor = (uint32_t)(brow & 7);
    const uint32_t aof = (uint32_t)arow * 128u;
    const uint32_t bof = 16384u + (uint32_t)brow * 128u;
    const uint32_t acs = (uint32_t)(lane >> 4);
    const uint32_t bcs = (uint32_t)((lane >> 3) & 1);
    const int b = b0 + mg;
    const int dq = lane >> 2, hq = (lane & 3) * 2;

    int cs = 0; uint32_t cph = 0;
    for (int L = 0; L < 3; L++) {
        const int NC = ncs[L];
        const float* bias = (L == 0) ? bias0 : (L == 1) ? bias1 : bias2;
        const int fcoff = (L == 0) ? 0 : (L == 1) ? 128 : 256;

        float acc[4][8][4];
#pragma unroll
        for (int i = 0; i < 4; i++)
#pragma unroll
            for (int j = 0; j < 8; j++)
#pragma unroll
                for (int q = 0; q < 4; q++) acc[i][j][q] = 0.0f;

        for (int c = 0; c < NC; c++) {
            mbar_wait(sb + 16 * cs, cph);       // stage full
            const int s = cs;
            if (++cs == 3) { cs = 0; cph ^= 1u; }
            const uint32_t stg = stg0 + (uint32_t)s * 49152u;
#pragma unroll
            for (int ks = 0; ks < 4; ks++) {
                uint32_t af[4][4], bf[4][4];
#pragma unroll
                for (int mt = 0; mt < 4; mt++)
                    ldsm4(af[mt], stg + aof + (uint32_t)(mt * 16 * 128) +
                                  ((((uint32_t)(2 * ks) + acs) ^ axor) << 4));
#pragma unroll
                for (int np = 0; np < 4; np++)
                    ldsm4(bf[np], stg + bof + (uint32_t)(np * 16 * 128) +
                                  ((((uint32_t)(2 * ks) + bcs) ^ bxor) << 4));
#pragma unroll
                for (int mt = 0; mt < 4; mt++)
#pragma unroll
                    for (int nt = 0; nt < 8; nt++)
                        mma16(acc[mt][nt], af[mt], &bf[nt >> 1][(nt & 1) * 2]);
            }
            mbar_arrive(sb + 16 * s + 8);       // stage consumed
        }

        // ---- epilogue ----
        if (L == 2 || ng < 2) {                 // fused fc dot
            float p = 0.0f;
#pragma unroll
            for (int nt = 0; nt < 8; nt++) {
                const int h = ng * 64 + nt * 8 + hq;
                const float bv0 = __ldg(bias + h), bv1 = __ldg(bias + h + 1);
                const float w0 = __ldg(fcW + fcoff + h), w1 = __ldg(fcW + fcoff + h + 1);
                float s0 = 0.0f, s1 = 0.0f;
#pragma unroll
                for (int mt = 0; mt < 4; mt++) {
                    s0 += fmaxf(acc[mt][nt][0] + bv0, 0.f) + fmaxf(acc[mt][nt][2] + bv0, 0.f);
                    s1 += fmaxf(acc[mt][nt][1] + bv1, 0.f) + fmaxf(acc[mt][nt][3] + bv1, 0.f);
                }
                p += s0 * w0 + s1 * w1;
            }
#pragma unroll
            for (int o = 16; o > 0; o >>= 1) p += __shfl_xor_sync(0xFFFFFFFFu, p, o);
            if (lane == 0) atomicAdd(out + b, p);
        }
        if (L < 2 && ng >= 2) {                 // h (next-layer input) -> SMEM hbuf
            float* yo = hb + (size_t)mg * 8192;
#pragma unroll
            for (int mt = 0; mt < 4; mt++) {
                const int d = mt * 16 + dq;
#pragma unroll
                for (int nt = 0; nt < 8; nt++) {
                    const int h = ng * 64 + nt * 8 + hq;
                    const float bv0 = __ldg(bias + h), bv1 = __ldg(bias + h + 1);
                    const int n = h - 128;
                    yo[(size_t)n * 64 + d]           = fmaxf(acc[mt][nt][0] + bv0, 0.f);
                    yo[(size_t)(n + 1) * 64 + d]     = fmaxf(acc[mt][nt][1] + bv1, 0.f);
                    yo[(size_t)n * 64 + d + 8]       = fmaxf(acc[mt][nt][2] + bv0, 0.f);
                    yo[(size_t)(n + 1) * 64 + d + 8] = fmaxf(acc[mt][nt][3] + bv1, 0.f);
                }
            }
        }
        if (L < 2) mbar_arrive(sb + 48);        // hbuf ready for producer (release)
    }
}

extern "C" void kernel_launch(void* const* d_in, const int* in_sizes, int n_in,
                              void* d_out, int out_size) {
    const float* x   = (const float*)d_in[0];
    const float* W0  = (const float*)d_in[1];
    const float* b0  = (const float*)d_in[2];
    const float* W1  = (const float*)d_in[3];
    const float* b1  = (const float*)d_in[4];
    const float* W2  = (const float*)d_in[5];
    const float* b2  = (const float*)d_in[6];
    const float* fcW = (const float*)d_in[7];
    const float* fcb = (const float*)d_in[8];
    float* out = (float*)d_out;

    // pad + mbar header + 3 stages + 64KB hbuf
    constexpr int SMEMSZ = 1024 + 1024 + 3 * 49152 + 65536;
    cudaFuncSetAttribute(cin_fused, cudaFuncAttributeMaxDynamicSharedMemorySize, SMEMSZ);

    __half *wt0p, *wt1p, *wt2p;
    cudaGetSymbolAddress((void**)&wt0p, g_wt0);
    cudaGetSymbolAddress((void**)&wt1p, g_wt1);
    cudaGetSymbolAddress((void**)&wt2p, g_wt2);

    wtrans<32>  <<<16, 256>>>(W0, wt0p);
    wtrans<128> <<<64, 256>>>(W1, wt1p);
    wtrans<128> <<<64, 256>>>(W2, wt2p);
    init_out<<<4, 256>>>(fcb, out);

    cin_fused<<<512, 320, SMEMSZ>>>(x, b0, b1, b2, fcW, out);
}

// round 10
// speedup vs baseline: 1.3765x; 1.1104x over previous
#include <cuda_runtime.h>
#include <cuda_fp16.h>
#include <cstdint>

// ---------------- device scratch (no allocations allowed) ----------------
// h>=128 rows of layers 0/1 outputs (next-layer hprev).
__device__ float  g_h0[1024 * 128 * 64];
__device__ float  g_h1[1024 * 128 * 64];
// Transposed fp16 weights, chunk-tiled (chunk = 64 k'):
// Wt[c][h][kk], kk = nl*32 + m (nl=0..1), n = 2c + nl, original k = m*NIN + n.
__device__ __half g_wt0[256 * 1024];
__device__ __half g_wt1[256 * 4096];
__device__ __half g_wt2[256 * 4096];

__device__ __forceinline__ uint32_t smem_u32(const void* p) {
    uint32_t r;
    asm("{ .reg .u64 t; cvta.to.shared.u64 t, %1; cvt.u32.u64 %0, t; }" : "=r"(r) : "l"(p));
    return r;
}
__device__ __forceinline__ uint32_t h2u(__half2 v) { return *reinterpret_cast<uint32_t*>(&v); }
__device__ __forceinline__ void cp16(uint32_t dst, const void* src) {
    asm volatile("cp.async.cg.shared.global [%0], [%1], 16;" :: "r"(dst), "l"(src) : "memory");
}
__device__ __forceinline__ void cp_mbar_arrive(uint32_t mbar) {
    asm volatile("cp.async.mbarrier.arrive.noinc.shared.b64 [%0];" :: "r"(mbar) : "memory");
}
__device__ __forceinline__ void mbar_init(uint32_t a, uint32_t c) {
    asm volatile("mbarrier.init.shared.b64 [%0], %1;" :: "r"(a), "r"(c) : "memory");
}
__device__ __forceinline__ void mbar_arrive(uint32_t a) {
    asm volatile("mbarrier.arrive.shared.b64 _, [%0];" :: "r"(a) : "memory");
}
__device__ __forceinline__ void mbar_wait(uint32_t a, uint32_t ph) {
    asm volatile(
        "{\n\t.reg .pred P;\n"
        "W_%=:\n\t"
        "mbarrier.try_wait.parity.shared.b64 P, [%0], %1, 0x989680;\n\t"
        "@P bra.uni D_%=;\n\t"
        "bra.uni W_%=;\n"
        "D_%=:\n\t}"
        :: "r"(a), "r"(ph) : "memory");
}
__device__ __forceinline__ void ldsm4(uint32_t* r, uint32_t a) {
    asm volatile("ldmatrix.sync.aligned.m8n8.x4.shared.b16 {%0,%1,%2,%3}, [%4];"
                 : "=r"(r[0]), "=r"(r[1]), "=r"(r[2]), "=r"(r[3]) : "r"(a));
}
__device__ __forceinline__ void mma16(float* c, const uint32_t* a, const uint32_t* b) {
    asm volatile("mma.sync.aligned.m16n8k16.row.col.f32.f16.f16.f32 "
                 "{%0,%1,%2,%3},{%4,%5,%6,%7},{%8,%9},{%0,%1,%2,%3};"
                 : "+f"(c[0]), "+f"(c[1]), "+f"(c[2]), "+f"(c[3])
                 : "r"(a[0]), "r"(a[1]), "r"(a[2]), "r"(a[3]), "r"(b[0]), "r"(b[1]));
}

// ---------------- weight transpose (fp16, chunk-64 tiling, coalesced) ----------------
template <int NIN>
__global__ void __launch_bounds__(256) wtrans(const float* __restrict__ W, __half* __restrict__ Wt) {
    __shared__ __half s[64 * 256];
    const int c = blockIdx.x, t = threadIdx.x;
#pragma unroll 4
    for (int kk = 0; kk < 64; kk++) {
        int m = kk & 31, nl = kk >> 5;
        int n = 2 * c + nl;
        int k = m * NIN + n;
        s[kk * 256 + t] = __float2half_rn(W[(size_t)k * 256 + t]);
    }
    __syncthreads();
    __half* dst = Wt + (size_t)c * 16384 + (size_t)t * 64;
#pragma unroll
    for (int j = 0; j < 8; j++) {
        uint4 v;
        v.x = h2u(__halves2half2(s[(8 * j + 0) * 256 + t], s[(8 * j + 1) * 256 + t]));
        v.y = h2u(__halves2half2(s[(8 * j + 2) * 256 + t], s[(8 * j + 3) * 256 + t]));
        v.z = h2u(__halves2half2(s[(8 * j + 4) * 256 + t], s[(8 * j + 5) * 256 + t]));
        v.w = h2u(__halves2half2(s[(8 * j + 6) * 256 + t], s[(8 * j + 7) * 256 + t]));
        *reinterpret_cast<uint4*>(dst + 8 * j) = v;
    }
}

__global__ void init_out(const float* __restrict__ fcb, float* __restrict__ out) {
    out[blockIdx.x * 256 + threadIdx.x] = fcb[0];
}

// ---------------- CIN layer: warp-specialized fp16 mma.sync, M128 x N128 tiles ----------------
// Grid 1024 = (batch-pair) x (h-segment of 128). 192 threads:
//   warps 0-3 = consumers (2x2 grid, warp tile 64d x 64h); warps 4-5 = producers.
// K-chunk 64 (2 n). Stage (32KB): A[128 x 128B] @0, B[128 x 128B] @16384. 3 stages.
// 2 CTAs/SM (98KB SMEM, <=170 regs) -> cross-CTA latency hiding + fine wave packing.
// full[s]: 128 arrivals (64 cp-completions + 64 A arrives). empty[s]: 128.
template <int L>
__global__ void __launch_bounds__(192, 2)
cin_layer(const float* __restrict__ x, const float* __restrict__ bias,
          const float* __restrict__ fcW, float* __restrict__ out) {
    constexpr int NIN = (L == 0) ? 32 : 128;
    constexpr int NC  = NIN / 2;                 // chunks of 64 k'
    const __half* wt  = (L == 0) ? g_wt0 : (L == 1) ? g_wt1 : g_wt2;
    const float* hbas = (L == 0) ? x : (L == 1) ? g_h0 : g_h1;
    const int hstr    = (L == 0) ? 2048 : 8192;

    extern __shared__ char smc[];
    const uint32_t sb0 = smem_u32(smc);
    const uint32_t sb  = (sb0 + 1023u) & ~1023u;
    char* const smb    = smc + (sb - sb0);
    const uint32_t stg0 = sb + 1024u;

    const int t = threadIdx.x, lane = t & 31, wid = t >> 5;
    const int b0   = (blockIdx.x >> 1) * 2;
    const int hseg = (blockIdx.x & 1) * 128;

    if (t == 0) {
#pragma unroll
        for (int s = 0; s < 3; s++) {
            mbar_init(sb + 16 * s, 128);       // full: 64 cp + 64 A
            mbar_init(sb + 16 * s + 8, 128);   // empty: 128 consumer threads
        }
    }
    __syncthreads();

    if (t >= 128) {
        // ================= producers (warps 4-5) =================
        const int ptid = t - 128;              // 0..63 (= d)
        float xr0[32], xr1[32];
        {
            const float* xp0 = x + (size_t)b0 * 2048 + ptid;
            const float* xp1 = x + (size_t)(b0 + 1) * 2048 + ptid;
#pragma unroll
            for (int m = 0; m < 32; m++) { xr0[m] = xp0[m * 64]; xr1[m] = xp1[m * 64]; }
        }
        const float* hp0 = hbas + (size_t)b0 * hstr + ptid;
        const float* hp1 = hbas + (size_t)(b0 + 1) * hstr + ptid;

        int ps = 0; uint32_t pph = 1;
        for (int c = 0; c < NC; c++) {
            mbar_wait(sb + 16 * ps + 8, pph);   // stage free
            const int s = ps;
            if (++ps == 3) { ps = 0; pph ^= 1u; }
            const uint32_t stg = stg0 + (uint32_t)s * 32768u;
            // B: this CTA's 128 h rows = 1024 x 16B chunks over 64 threads -> 16 cp16.
            const __half* ws = wt + (size_t)c * 16384 + (size_t)hseg * 64;
#pragma unroll
            for (int i = 0; i < 16; i++) {
                const int p = ptid + i * 64;
                const int h = p >> 3, j = p & 7;
                cp16(stg + 16384u + (uint32_t)h * 128u + (uint32_t)((j ^ (h & 7)) << 4),
                     ws + (size_t)h * 64 + j * 8);
            }
            cp_mbar_arrive(sb + 16 * s);
            // A: rows ptid (batch b0) and ptid+64 (batch b0+1).
#pragma unroll
            for (int r2 = 0; r2 < 2; r2++) {
                const int row = ptid + r2 * 64;
                const float* xr = r2 ? xr1 : xr0;
                const float* hp = r2 ? hp1 : hp0;
                const uint32_t asw = (uint32_t)(row & 7);
                char* ab = smb + (stg - sb) + (uint32_t)row * 128u;
#pragma unroll
                for (int nl = 0; nl < 2; nl++) {
                    const float hv = hp[(size_t)(2 * c + nl) * 64];
#pragma unroll
                    for (int u = 0; u < 4; u++) {
                        uint4 v;
                        v.x = h2u(__floats2half2_rn(xr[8*u+0]*hv, xr[8*u+1]*hv));
                        v.y = h2u(__floats2half2_rn(xr[8*u+2]*hv, xr[8*u+3]*hv));
                        v.z = h2u(__floats2half2_rn(xr[8*u+4]*hv, xr[8*u+5]*hv));
                        v.w = h2u(__floats2half2_rn(xr[8*u+6]*hv, xr[8*u+7]*hv));
                        const int j = nl * 4 + u;
                        *reinterpret_cast<uint4*>(ab + ((((uint32_t)j) ^ asw) << 4)) = v;
                    }
                }
            }
            mbar_arrive(sb + 16 * s);           // A ready (release)
        }
        return;
    }

    // ================= consumers (warps 0-3) =================
    const int mg = wid >> 1, ng = wid & 1;      // 2x2 grid of 64x64 tiles
    const int arow = mg * 64 + (lane & 15);
    const int brow = ng * 64 + ((lane >> 4) << 3) + (lane & 7);
    const uint32_t axor = (uint32_t)(arow & 7);
    const uint32_t bxor = (uint32_t)(brow & 7);
    const uint32_t aof = (uint32_t)arow * 128u;
    const uint32_t bof = 16384u + (uint32_t)brow * 128u;
    const uint32_t acs = (uint32_t)(lane >> 4);
    const uint32_t bcs = (uint32_t)((lane >> 3) & 1);

    float acc[4][8][4];
#pragma unroll
    for (int i = 0; i < 4; i++)
#pragma unroll
        for (int j = 0; j < 8; j++)
#pragma unroll
            for (int q = 0; q < 4; q++) acc[i][j][q] = 0.0f;

    int cs = 0; uint32_t cph = 0;
    for (int c = 0; c < NC; c++) {
        mbar_wait(sb + 16 * cs, cph);           // stage full
        const int s = cs;
        if (++cs == 3) { cs = 0; cph ^= 1u; }
        const uint32_t stg = stg0 + (uint32_t)s * 32768u;
#pragma unroll
        for (int ks = 0; ks < 4; ks++) {
            uint32_t af[4][4], bf[4][4];
#pragma unroll
            for (int mt = 0; mt < 4; mt++)
                ldsm4(af[mt], stg + aof + (uint32_t)(mt * 16 * 128) +
                              ((((uint32_t)(2 * ks) + acs) ^ axor) << 4));
#pragma unroll
            for (int np = 0; np < 4; np++)
                ldsm4(bf[np], stg + bof + (uint32_t)(np * 16 * 128) +
                              ((((uint32_t)(2 * ks) + bcs) ^ bxor) << 4));
#pragma unroll
            for (int mt = 0; mt < 4; mt++)
#pragma unroll
                for (int nt = 0; nt < 8; nt++)
                    mma16(acc[mt][nt], af[mt], &bf[nt >> 1][(nt & 1) * 2]);
        }
        mbar_arrive(sb + 16 * s + 8);           // stage consumed
    }

    // ---- epilogue: bias+relu. h-global = hseg + local.
    //      L<2, hseg==0  -> all rows feed the fused fc dot.
    //      L<2, hseg==128-> rows are next layer's hprev -> g_h.
    //      L==2          -> all rows feed the fc dot. ----
    const int b = b0 + mg;
    const int dq = lane >> 2, hq = (lane & 3) * 2;
    if (L == 2 || hseg == 0) {
        const int fcoff = (L == 0) ? 0 : (L == 1) ? 128 : 256 + hseg;
        float p = 0.0f;
#pragma unroll
        for (int nt = 0; nt < 8; nt++) {
            const int hl = ng * 64 + nt * 8 + hq;
            const float bv0 = __ldg(bias + hseg + hl), bv1 = __ldg(bias + hseg + hl + 1);
            const float w0 = __ldg(fcW + fcoff + hl), w1 = __ldg(fcW + fcoff + hl + 1);
            float s0 = 0.0f, s1 = 0.0f;
#pragma unroll
            for (int mt = 0; mt < 4; mt++) {
                s0 += fmaxf(acc[mt][nt][0] + bv0, 0.f) + fmaxf(acc[mt][nt][2] + bv0, 0.f);
                s1 += fmaxf(acc[mt][nt][1] + bv1, 0.f) + fmaxf(acc[mt][nt][3] + bv1, 0.f);
            }
            p += s0 * w0 + s1 * w1;
        }
#pragma unroll
        for (int o = 16; o > 0; o >>= 1) p += __shfl_xor_sync(0xFFFFFFFFu, p, o);
        if (lane == 0) atomicAdd(out + b, p);
    } else {
        float* yo = (L == 0 ? g_h0 : g_h1) + (size_t)b * 8192;
#pragma unroll
        for (int mt = 0; mt < 4; mt++) {
            const int d = mt * 16 + dq;
#pragma unroll
            for (int nt = 0; nt < 8; nt++) {
                const int hl = ng * 64 + nt * 8 + hq;       // = n (local row of g_h)
                const float bv0 = __ldg(bias + 128 + hl), bv1 = __ldg(bias + 128 + hl + 1);
                yo[(size_t)hl * 64 + d]           = fmaxf(acc[mt][nt][0] + bv0, 0.f);
                yo[(size_t)(hl + 1) * 64 + d]     = fmaxf(acc[mt][nt][1] + bv1, 0.f);
                yo[(size_t)hl * 64 + d + 8]       = fmaxf(acc[mt][nt][2] + bv0, 0.f);
                yo[(size_t)(hl + 1) * 64 + d + 8] = fmaxf(acc[mt][nt][3] + bv1, 0.f);
            }
        }
    }
}

extern "C" void kernel_launch(void* const* d_in, const int* in_sizes, int n_in,
                              void* d_out, int out_size) {
    const float* x   = (const float*)d_in[0];
    const float* W0  = (const float*)d_in[1];
    const float* b0  = (const float*)d_in[2];
    const float* W1  = (const float*)d_in[3];
    const float* b1  = (const float*)d_in[4];
    const float* W2  = (const float*)d_in[5];
    const float* b2  = (const float*)d_in[6];
    const float* fcW = (const float*)d_in[7];
    const float* fcb = (const float*)d_in[8];
    float* out = (float*)d_out;

    // align pad + mbar header + 3 x 32KB stages = 98KB -> 2 CTAs/SM
    constexpr int SMEMSZ = 1024 + 1024 + 3 * 32768;
    cudaFuncSetAttribute(cin_layer<0>, cudaFuncAttributeMaxDynamicSharedMemorySize, SMEMSZ);
    cudaFuncSetAttribute(cin_layer<1>, cudaFuncAttributeMaxDynamicSharedMemorySize, SMEMSZ);
    cudaFuncSetAttribute(cin_layer<2>, cudaFuncAttributeMaxDynamicSharedMemorySize, SMEMSZ);

    __half *wt0p, *wt1p, *wt2p;
    cudaGetSymbolAddress((void**)&wt0p, g_wt0);
    cudaGetSymbolAddress((void**)&wt1p, g_wt1);
    cudaGetSymbolAddress((void**)&wt2p, g_wt2);

    wtrans<32>  <<<16, 256>>>(W0, wt0p);
    wtrans<128> <<<64, 256>>>(W1, wt1p);
    wtrans<128> <<<64, 256>>>(W2, wt2p);
    init_out<<<4, 256>>>(fcb, out);

    cin_layer<0><<<1024, 192, SMEMSZ>>>(x, b0, fcW, out);
    cin_layer<1><<<1024, 192, SMEMSZ>>>(x, b1, fcW, out);
    cin_layer<2><<<1024, 192, SMEMSZ>>>(x, b2, fcW, out);
}

// round 11
// speedup vs baseline: 1.3949x; 1.0134x over previous
#include <cuda_runtime.h>
#include <cuda_fp16.h>
#include <cstdint>

// ---------------- device scratch (no allocations allowed) ----------------
// h>=128 rows of layers 0/1 outputs (next-layer hprev).
__device__ float  g_h0[1024 * 128 * 64];
__device__ float  g_h1[1024 * 128 * 64];
// Transposed fp16 weights, chunk-tiled (chunk = 64 k').
// L0 (symmetry-folded): chunk c, kk -> pair p = 64c+kk, p indexes (m<=n) pairs
//   (528 real + padding to 576); Wt0[c][h][kk] = W0[m*32+n][h] + (m<n)*W0[n*32+m][h].
// L1/L2: kk = nl*32 + m (nl=0..1), n = 2c + nl, original k = m*128 + n.
__device__ __half g_wt0[9 * 16384];
__device__ __half g_wt1[256 * 4096];
__device__ __half g_wt2[256 * 4096];

__device__ __forceinline__ uint32_t smem_u32(const void* p) {
    uint32_t r;
    asm("{ .reg .u64 t; cvta.to.shared.u64 t, %1; cvt.u32.u64 %0, t; }" : "=r"(r) : "l"(p));
    return r;
}
__device__ __forceinline__ uint32_t h2u(__half2 v) { return *reinterpret_cast<uint32_t*>(&v); }
__device__ __forceinline__ void cp16(uint32_t dst, const void* src) {
    asm volatile("cp.async.cg.shared.global [%0], [%1], 16;" :: "r"(dst), "l"(src) : "memory");
}
__device__ __forceinline__ void cp_mbar_arrive(uint32_t mbar) {
    asm volatile("cp.async.mbarrier.arrive.noinc.shared.b64 [%0];" :: "r"(mbar) : "memory");
}
__device__ __forceinline__ void mbar_init(uint32_t a, uint32_t c) {
    asm volatile("mbarrier.init.shared.b64 [%0], %1;" :: "r"(a), "r"(c) : "memory");
}
__device__ __forceinline__ void mbar_arrive(uint32_t a) {
    asm volatile("mbarrier.arrive.shared.b64 _, [%0];" :: "r"(a) : "memory");
}
__device__ __forceinline__ void mbar_wait(uint32_t a, uint32_t ph) {
    asm volatile(
        "{\n\t.reg .pred P;\n"
        "W_%=:\n\t"
        "mbarrier.try_wait.parity.shared.b64 P, [%0], %1, 0x989680;\n\t"
        "@P bra.uni D_%=;\n\t"
        "bra.uni W_%=;\n"
        "D_%=:\n\t}"
        :: "r"(a), "r"(ph) : "memory");
}
__device__ __forceinline__ void ldsm4(uint32_t* r, uint32_t a) {
    asm volatile("ldmatrix.sync.aligned.m8n8.x4.shared.b16 {%0,%1,%2,%3}, [%4];"
                 : "=r"(r[0]), "=r"(r[1]), "=r"(r[2]), "=r"(r[3]) : "r"(a));
}
__device__ __forceinline__ void mma16(float* c, const uint32_t* a, const uint32_t* b) {
    asm volatile("mma.sync.aligned.m16n8k16.row.col.f32.f16.f16.f32 "
                 "{%0,%1,%2,%3},{%4,%5,%6,%7},{%8,%9},{%0,%1,%2,%3};"
                 : "+f"(c[0]), "+f"(c[1]), "+f"(c[2]), "+f"(c[3])
                 : "r"(a[0]), "r"(a[1]), "r"(a[2]), "r"(a[3]), "r"(b[0]), "r"(b[1]));
}
// triangular base: # of pairs (m',n') with m'<m  (n'>=m')
__device__ __forceinline__ int tribase(int m) { return 32 * m - ((m * (m - 1)) >> 1); }

// ---------------- prep: all weight transposes + out init in ONE launch ----------------
// blocks 0-8: folded L0 chunks; 9-72: L1 chunks; 73-136: L2 chunks; 137-140: out init.
__global__ void __launch_bounds__(256)
prep(const float* __restrict__ W0, const float* __restrict__ W1, const float* __restrict__ W2,
     const float* __restrict__ fcb, float* __restrict__ out,
     __half* __restrict__ wt0, __half* __restrict__ wt1, __half* __restrict__ wt2) {
    const int bx = blockIdx.x, t = threadIdx.x;
    if (bx >= 137) { out[(bx - 137) * 256 + t] = fcb[0]; return; }

    __shared__ __half s[64 * 256];
    __half* dst;
    if (bx < 9) {
        // L0 folded: chunk c, pairs p = 64c..64c+63.
        const int c = bx, p0 = 64 * c;
        int m = 0;
        while (tribase(m + 1) <= p0) ++m;
        int n = m + (p0 - tribase(m));
        for (int kk = 0; kk < 64; kk++) {
            float v = 0.0f;
            if (p0 + kk < 528) {
                v = W0[(size_t)(m * 32 + n) * 256 + t];
                if (n > m) v += W0[(size_t)(n * 32 + m) * 256 + t];
                if (++n == 32) { ++m; n = m; }
            }
            s[kk * 256 + t] = __float2half_rn(v);
        }
        dst = wt0 + (size_t)c * 16384 + (size_t)t * 64;
    } else {
        const int c = (bx < 73) ? (bx - 9) : (bx - 73);
        const float* W = (bx < 73) ? W1 : W2;
#pragma unroll 4
        for (int kk = 0; kk < 64; kk++) {
            const int m = kk & 31, nl = kk >> 5;
            const int k = m * 128 + 2 * c + nl;
            s[kk * 256 + t] = __float2half_rn(W[(size_t)k * 256 + t]);
        }
        dst = ((bx < 73) ? wt1 : wt2) + (size_t)c * 16384 + (size_t)t * 64;
    }
    __syncthreads();
#pragma unroll
    for (int j = 0; j < 8; j++) {
        uint4 v;
        v.x = h2u(__halves2half2(s[(8 * j + 0) * 256 + t], s[(8 * j + 1) * 256 + t]));
        v.y = h2u(__halves2half2(s[(8 * j + 2) * 256 + t], s[(8 * j + 3) * 256 + t]));
        v.z = h2u(__halves2half2(s[(8 * j + 4) * 256 + t], s[(8 * j + 5) * 256 + t]));
        v.w = h2u(__halves2half2(s[(8 * j + 6) * 256 + t], s[(8 * j + 7) * 256 + t]));
        *reinterpret_cast<uint4*>(dst + 8 * j) = v;
    }
}

// ---------------- CIN layer: warp-specialized fp16 mma.sync, M128 x N128 tiles ----------------
// Grid 1024 = (batch-pair) x (h-segment of 128). 192 threads:
//   warps 0-3 = consumers (2x2 grid, warp tile 64d x 64h); warps 4-5 = producers.
// K-chunk 64. L0 uses folded pairs (NC=9), L1/L2 rectangular (NC=64).
// Stage (32KB): A[128 x 128B] @0, B[128 x 128B] @16384. 3 stages. 2 CTAs/SM.
// full[s]: 128 arrivals (64 cp-completions + 64 A arrives). empty[s]: 128.
template <int L>
__global__ void __launch_bounds__(192, 2)
cin_layer(const float* __restrict__ x, const float* __restrict__ bias,
          const float* __restrict__ fcW, float* __restrict__ out) {
    constexpr int NC  = (L == 0) ? 9 : 64;
    const __half* wt  = (L == 0) ? g_wt0 : (L == 1) ? g_wt1 : g_wt2;
    const float* hbas = (L == 1) ? g_h0 : g_h1;   // L0 never reads this

    extern __shared__ char smc[];
    const uint32_t sb0 = smem_u32(smc);
    const uint32_t sb  = (sb0 + 1023u) & ~1023u;
    char* const smb    = smc + (sb - sb0);
    const uint32_t stg0 = sb + 1024u;

    const int t = threadIdx.x, lane = t & 31, wid = t >> 5;
    const int b0   = (blockIdx.x >> 1) * 2;
    const int hseg = (blockIdx.x & 1) * 128;

    if (t == 0) {
#pragma unroll
        for (int s = 0; s < 3; s++) {
            mbar_init(sb + 16 * s, 128);       // full: 64 cp + 64 A
            mbar_init(sb + 16 * s + 8, 128);   // empty: 128 consumer threads
        }
    }
    __syncthreads();

    if (t >= 128) {
        // ================= producers (warps 4-5) =================
        const int ptid = t - 128;              // 0..63 (= d)
        float xr0[32], xr1[32];
        {
            const float* xp0 = x + (size_t)b0 * 2048 + ptid;
            const float* xp1 = x + (size_t)(b0 + 1) * 2048 + ptid;
#pragma unroll
            for (int m = 0; m < 32; m++) { xr0[m] = xp0[m * 64]; xr1[m] = xp1[m * 64]; }
        }
        const float* hp0 = hbas + (size_t)b0 * 8192 + ptid;
        const float* hp1 = hbas + (size_t)(b0 + 1) * 8192 + ptid;

        int ps = 0; uint32_t pph = 1;
        for (int c = 0; c < NC; c++) {
            mbar_wait(sb + 16 * ps + 8, pph);   // stage free
            const int s = ps;
            if (++ps == 3) { ps = 0; pph ^= 1u; }
            const uint32_t stg = stg0 + (uint32_t)s * 32768u;
            // B: this CTA's 128 h rows = 1024 x 16B chunks over 64 threads -> 16 cp16.
            const __half* ws = wt + (size_t)c * 16384 + (size_t)hseg * 64;
#pragma unroll
            for (int i = 0; i < 16; i++) {
                const int p = ptid + i * 64;
                const int h = p >> 3, j = p & 7;
                cp16(stg + 16384u + (uint32_t)h * 128u + (uint32_t)((j ^ (h & 7)) << 4),
                     ws + (size_t)h * 64 + j * 8);
            }
            cp_mbar_arrive(sb + 16 * s);
            // A: rows ptid (batch b0) and ptid+64 (batch b0+1).
            if (L == 0) {
                // folded pairs: A[row][kk] = x[m]*x[n], p = 64c+kk.
                int m0 = 0;
                while (tribase(m0 + 1) <= 64 * c) ++m0;
                const int n0 = m0 + (64 * c - tribase(m0));
#pragma unroll
                for (int r2 = 0; r2 < 2; r2++) {
                    const int row = ptid + r2 * 64;
                    const float* xr = r2 ? xr1 : xr0;
                    const uint32_t asw = (uint32_t)(row & 7);
                    char* ab = smb + (stg - sb) + (uint32_t)row * 128u;
                    int m = m0, n = n0;
#pragma unroll
                    for (int j = 0; j < 8; j++) {
                        float f[8];
#pragma unroll
                        for (int q = 0; q < 8; q++) {
                            if (64 * c + 8 * j + q < 528) {
                                f[q] = xr[m] * xr[n];
                                if (++n == 32) { ++m; n = m; }
                            } else f[q] = 0.0f;
                        }
                        uint4 v;
                        v.x = h2u(__floats2half2_rn(f[0], f[1]));
                        v.y = h2u(__floats2half2_rn(f[2], f[3]));
                        v.z = h2u(__floats2half2_rn(f[4], f[5]));
                        v.w = h2u(__floats2half2_rn(f[6], f[7]));
                        *reinterpret_cast<uint4*>(ab + ((((uint32_t)j) ^ asw) << 4)) = v;
                    }
                }
            } else {
#pragma unroll
                for (int r2 = 0; r2 < 2; r2++) {
                    const int row = ptid + r2 * 64;
                    const float* xr = r2 ? xr1 : xr0;
                    const float* hp = r2 ? hp1 : hp0;
                    const uint32_t asw = (uint32_t)(row & 7);
                    char* ab = smb + (stg - sb) + (uint32_t)row * 128u;
#pragma unroll
                    for (int nl = 0; nl < 2; nl++) {
                        const float hv = hp[(size_t)(2 * c + nl) * 64];
#pragma unroll
                        for (int u = 0; u < 4; u++) {
                            uint4 v;
                            v.x = h2u(__floats2half2_rn(xr[8*u+0]*hv, xr[8*u+1]*hv));
                            v.y = h2u(__floats2half2_rn(xr[8*u+2]*hv, xr[8*u+3]*hv));
                            v.z = h2u(__floats2half2_rn(xr[8*u+4]*hv, xr[8*u+5]*hv));
                            v.w = h2u(__floats2half2_rn(xr[8*u+6]*hv, xr[8*u+7]*hv));
                            const int j = nl * 4 + u;
                            *reinterpret_cast<uint4*>(ab + ((((uint32_t)j) ^ asw) << 4)) = v;
                        }
                    }
                }
            }
            mbar_arrive(sb + 16 * s);           // A ready (release)
        }
        return;
    }

    // ================= consumers (warps 0-3) =================
    const int mg = wid >> 1, ng = wid & 1;      // 2x2 grid of 64x64 tiles
    const int arow = mg * 64 + (lane & 15);
    const int brow = ng * 64 + ((lane >> 4) << 3) + (lane & 7);
    const uint32_t axor = (uint32_t)(arow & 7);
    const uint32_t bxor = (uint32_t)(brow & 7);
    const uint32_t aof = (uint32_t)arow * 128u;
    const uint32_t bof = 16384u + (uint32_t)brow * 128u;
    const uint32_t acs = (uint32_t)(lane >> 4);
    const uint32_t bcs = (uint32_t)((lane >> 3) & 1);

    float acc[4][8][4];
#pragma unroll
    for (int i = 0; i < 4; i++)
#pragma unroll
        for (int j = 0; j < 8; j++)
#pragma unroll
            for (int q = 0; q < 4; q++) acc[i][j][q] = 0.0f;

    int cs = 0; uint32_t cph = 0;
    for (int c = 0; c < NC; c++) {
        mbar_wait(sb + 16 * cs, cph);           // stage full
        const int s = cs;
        if (++cs == 3) { cs = 0; cph ^= 1u; }
        const uint32_t stg = stg0 + (uint32_t)s * 32768u;
#pragma unroll
        for (int ks = 0; ks < 4; ks++) {
            uint32_t af[4][4], bf[4][4];
#pragma unroll
            for (int mt = 0; mt < 4; mt++)
                ldsm4(af[mt], stg + aof + (uint32_t)(mt * 16 * 128) +
                              ((((uint32_t)(2 * ks) + acs) ^ axor) << 4));
#pragma unroll
            for (int np = 0; np < 4; np++)
                ldsm4(bf[np], stg + bof + (uint32_t)(np * 16 * 128) +
                              ((((uint32_t)(2 * ks) + bcs) ^ bxor) << 4));
#pragma unroll
            for (int mt = 0; mt < 4; mt++)
#pragma unroll
                for (int nt = 0; nt < 8; nt++)
                    mma16(acc[mt][nt], af[mt], &bf[nt >> 1][(nt & 1) * 2]);
        }
        mbar_arrive(sb + 16 * s + 8);           // stage consumed
    }

    // ---- epilogue: bias+relu. h-global = hseg + local.
    //      L<2, hseg==0  -> fused fc dot; L<2, hseg==128 -> g_h write; L==2 -> fc dot. ----
    const int b = b0 + mg;
    const int dq = lane >> 2, hq = (lane & 3) * 2;
    if (L == 2 || hseg == 0) {
        const int fcoff = (L == 0) ? 0 : (L == 1) ? 128 : 256 + hseg;
        float p = 0.0f;
#pragma unroll
        for (int nt = 0; nt < 8; nt++) {
            const int hl = ng * 64 + nt * 8 + hq;
            const float bv0 = __ldg(bias + hseg + hl), bv1 = __ldg(bias + hseg + hl + 1);
            const float w0 = __ldg(fcW + fcoff + hl), w1 = __ldg(fcW + fcoff + hl + 1);
            float s0 = 0.0f, s1 = 0.0f;
#pragma unroll
            for (int mt = 0; mt < 4; mt++) {
                s0 += fmaxf(acc[mt][nt][0] + bv0, 0.f) + fmaxf(acc[mt][nt][2] + bv0, 0.f);
                s1 += fmaxf(acc[mt][nt][1] + bv1, 0.f) + fmaxf(acc[mt][nt][3] + bv1, 0.f);
            }
            p += s0 * w0 + s1 * w1;
        }
#pragma unroll
        for (int o = 16; o > 0; o >>= 1) p += __shfl_xor_sync(0xFFFFFFFFu, p, o);
        if (lane == 0) atomicAdd(out + b, p);
    } else {
        float* yo = (L == 0 ? g_h0 : g_h1) + (size_t)b * 8192;
#pragma unroll
        for (int mt = 0; mt < 4; mt++) {
            const int d = mt * 16 + dq;
#pragma unroll
            for (int nt = 0; nt < 8; nt++) {
                const int hl = ng * 64 + nt * 8 + hq;       // = n (local row of g_h)
                const float bv0 = __ldg(bias + 128 + hl), bv1 = __ldg(bias + 128 + hl + 1);
                yo[(size_t)hl * 64 + d]           = fmaxf(acc[mt][nt][0] + bv0, 0.f);
                yo[(size_t)(hl + 1) * 64 + d]     = fmaxf(acc[mt][nt][1] + bv1, 0.f);
                yo[(size_t)hl * 64 + d + 8]       = fmaxf(acc[mt][nt][2] + bv0, 0.f);
                yo[(size_t)(hl + 1) * 64 + d + 8] = fmaxf(acc[mt][nt][3] + bv1, 0.f);
            }
        }
    }
}

extern "C" void kernel_launch(void* const* d_in, const int* in_sizes, int n_in,
                              void* d_out, int out_size) {
    const float* x   = (const float*)d_in[0];
    const float* W0  = (const float*)d_in[1];
    const float* b0  = (const float*)d_in[2];
    const float* W1  = (const float*)d_in[3];
    const float* b1  = (const float*)d_in[4];
    const float* W2  = (const float*)d_in[5];
    const float* b2  = (const float*)d_in[6];
    const float* fcW = (const float*)d_in[7];
    const float* fcb = (const float*)d_in[8];
    float* out = (float*)d_out;

    // align pad + mbar header + 3 x 32KB stages = 98KB -> 2 CTAs/SM
    constexpr int SMEMSZ = 1024 + 1024 + 3 * 32768;
    cudaFuncSetAttribute(cin_layer<0>, cudaFuncAttributeMaxDynamicSharedMemorySize, SMEMSZ);
    cudaFuncSetAttribute(cin_layer<1>, cudaFuncAttributeMaxDynamicSharedMemorySize, SMEMSZ);
    cudaFuncSetAttribute(cin_layer<2>, cudaFuncAttributeMaxDynamicSharedMemorySize, SMEMSZ);

    __half *wt0p, *wt1p, *wt2p;
    cudaGetSymbolAddress((void**)&wt0p, g_wt0);
    cudaGetSymbolAddress((void**)&wt1p, g_wt1);
    cudaGetSymbolAddress((void**)&wt2p, g_wt2);

    prep<<<141, 256>>>(W0, W1, W2, fcb, out, wt0p, wt1p, wt2p);

    cin_layer<0><<<1024, 192, SMEMSZ>>>(x, b0, fcW, out);
    cin_layer<1><<<1024, 192, SMEMSZ>>>(x, b1, fcW, out);
    cin_layer<2><<<1024, 192, SMEMSZ>>>(x, b2, fcW, out);
}

// round 12
// speedup vs baseline: 1.3952x; 1.0002x over previous
#include <cuda_runtime.h>
#include <cuda_fp16.h>
#include <cstdint>

// ---------------- device scratch (no allocations allowed) ----------------
// h>=128 rows of layers 0/1 outputs (next-layer hprev).
__device__ float  g_h0[1024 * 128 * 64];
__device__ float  g_h1[1024 * 128 * 64];
// Transposed fp16 weights, chunk-tiled (chunk = 64 k').
// L0 (symmetry-folded): chunk c, kk -> pair p = 64c+kk, p indexes (m<=n) pairs
//   (528 real + padding to 576); Wt0[c][h][kk] = W0[m*32+n][h] + (m<n)*W0[n*32+m][h].
// L1/L2: kk = nl*32 + m (nl=0..1), n = 2c + nl, original k = m*128 + n.
__device__ __half g_wt0[9 * 16384];
__device__ __half g_wt1[256 * 4096];
__device__ __half g_wt2[256 * 4096];

__device__ __forceinline__ uint32_t smem_u32(const void* p) {
    uint32_t r;
    asm("{ .reg .u64 t; cvta.to.shared.u64 t, %1; cvt.u32.u64 %0, t; }" : "=r"(r) : "l"(p));
    return r;
}
__device__ __forceinline__ uint32_t h2u(__half2 v) { return *reinterpret_cast<uint32_t*>(&v); }
__device__ __forceinline__ void cp16(uint32_t dst, const void* src) {
    asm volatile("cp.async.cg.shared.global [%0], [%1], 16;" :: "r"(dst), "l"(src) : "memory");
}
__device__ __forceinline__ void cp_mbar_arrive(uint32_t mbar) {
    asm volatile("cp.async.mbarrier.arrive.noinc.shared.b64 [%0];" :: "r"(mbar) : "memory");
}
__device__ __forceinline__ void mbar_init(uint32_t a, uint32_t c) {
    asm volatile("mbarrier.init.shared.b64 [%0], %1;" :: "r"(a), "r"(c) : "memory");
}
__device__ __forceinline__ void mbar_arrive(uint32_t a) {
    asm volatile("mbarrier.arrive.shared.b64 _, [%0];" :: "r"(a) : "memory");
}
__device__ __forceinline__ void mbar_wait(uint32_t a, uint32_t ph) {
    asm volatile(
        "{\n\t.reg .pred P;\n"
        "W_%=:\n\t"
        "mbarrier.try_wait.parity.shared.b64 P, [%0], %1, 0x989680;\n\t"
        "@P bra.uni D_%=;\n\t"
        "bra.uni W_%=;\n"
        "D_%=:\n\t}"
        :: "r"(a), "r"(ph) : "memory");
}
__device__ __forceinline__ void ldsm4(uint32_t* r, uint32_t a) {
    asm volatile("ldmatrix.sync.aligned.m8n8.x4.shared.b16 {%0,%1,%2,%3}, [%4];"
                 : "=r"(r[0]), "=r"(r[1]), "=r"(r[2]), "=r"(r[3]) : "r"(a));
}
__device__ __forceinline__ void mma16(float* c, const uint32_t* a, const uint32_t* b) {
    asm volatile("mma.sync.aligned.m16n8k16.row.col.f32.f16.f16.f32 "
                 "{%0,%1,%2,%3},{%4,%5,%6,%7},{%8,%9},{%0,%1,%2,%3};"
                 : "+f"(c[0]), "+f"(c[1]), "+f"(c[2]), "+f"(c[3])
                 : "r"(a[0]), "r"(a[1]), "r"(a[2]), "r"(a[3]), "r"(b[0]), "r"(b[1]));
}
// triangular base: # of pairs (m',n') with m'<m  (n'>=m')
__device__ __forceinline__ int tribase(int m) { return 32 * m - ((m * (m - 1)) >> 1); }

// ---------------- prep: all weight transposes + out init in ONE launch ----------------
// blocks 0-8: folded L0 chunks; 9-72: L1 chunks; 73-136: L2 chunks; 137-140: out init.
__global__ void __launch_bounds__(256)
prep(const float* __restrict__ W0, const float* __restrict__ W1, const float* __restrict__ W2,
     const float* __restrict__ fcb, float* __restrict__ out,
     __half* __restrict__ wt0, __half* __restrict__ wt1, __half* __restrict__ wt2) {
    const int bx = blockIdx.x, t = threadIdx.x;
    if (bx >= 137) { out[(bx - 137) * 256 + t] = fcb[0]; return; }

    __shared__ __half s[64 * 256];
    __half* dst;
    if (bx < 9) {
        // L0 folded: chunk c, pairs p = 64c..64c+63.
        const int c = bx, p0 = 64 * c;
        int m = 0;
        while (tribase(m + 1) <= p0) ++m;
        int n = m + (p0 - tribase(m));
        for (int kk = 0; kk < 64; kk++) {
            float v = 0.0f;
            if (p0 + kk < 528) {
                v = W0[(size_t)(m * 32 + n) * 256 + t];
                if (n > m) v += W0[(size_t)(n * 32 + m) * 256 + t];
                if (++n == 32) { ++m; n = m; }
            }
            s[kk * 256 + t] = __float2half_rn(v);
        }
        dst = wt0 + (size_t)c * 16384 + (size_t)t * 64;
    } else {
        const int c = (bx < 73) ? (bx - 9) : (bx - 73);
        const float* W = (bx < 73) ? W1 : W2;
#pragma unroll 4
        for (int kk = 0; kk < 64; kk++) {
            const int m = kk & 31, nl = kk >> 5;
            const int k = m * 128 + 2 * c + nl;
            s[kk * 256 + t] = __float2half_rn(W[(size_t)k * 256 + t]);
        }
        dst = ((bx < 73) ? wt1 : wt2) + (size_t)c * 16384 + (size_t)t * 64;
    }
    __syncthreads();
#pragma unroll
    for (int j = 0; j < 8; j++) {
        uint4 v;
        v.x = h2u(__halves2half2(s[(8 * j + 0) * 256 + t], s[(8 * j + 1) * 256 + t]));
        v.y = h2u(__halves2half2(s[(8 * j + 2) * 256 + t], s[(8 * j + 3) * 256 + t]));
        v.z = h2u(__halves2half2(s[(8 * j + 4) * 256 + t], s[(8 * j + 5) * 256 + t]));
        v.w = h2u(__halves2half2(s[(8 * j + 6) * 256 + t], s[(8 * j + 7) * 256 + t]));
        *reinterpret_cast<uint4*>(dst + 8 * j) = v;
    }
}

// ---------------- CIN layer: warp-specialized fp16 mma.sync, M128 x N128 tiles ----------------
// Grid 1024 = (batch-pair) x (h-segment of 128). 192 threads:
//   warps 0-3 = consumers (2x2 grid, warp tile 64d x 64h); warps 4-5 = producers.
// K-chunk 64. L0 uses folded pairs (NC=9), L1/L2 rectangular (NC=64).
// Stage (32KB): A[128 x 128B] @0, B[128 x 128B] @16384. 3 stages. 2 CTAs/SM.
// full[s]: 128 arrivals (64 cp-completions + 64 A arrives). empty[s]: 128.
template <int L>
__global__ void __launch_bounds__(192, 2)
cin_layer(const float* __restrict__ x, const float* __restrict__ bias,
          const float* __restrict__ fcW, float* __restrict__ out) {
    constexpr int NC  = (L == 0) ? 9 : 64;
    const __half* wt  = (L == 0) ? g_wt0 : (L == 1) ? g_wt1 : g_wt2;
    const float* hbas = (L == 1) ? g_h0 : g_h1;   // L0 never reads this

    extern __shared__ char smc[];
    const uint32_t sb0 = smem_u32(smc);
    const uint32_t sb  = (sb0 + 1023u) & ~1023u;
    char* const smb    = smc + (sb - sb0);
    const uint32_t stg0 = sb + 1024u;

    const int t = threadIdx.x, lane = t & 31, wid = t >> 5;
    const int b0   = (blockIdx.x >> 1) * 2;
    const int hseg = (blockIdx.x & 1) * 128;

    if (t == 0) {
#pragma unroll
        for (int s = 0; s < 3; s++) {
            mbar_init(sb + 16 * s, 128);       // full: 64 cp + 64 A
            mbar_init(sb + 16 * s + 8, 128);   // empty: 128 consumer threads
        }
    }
    __syncthreads();

    if (t >= 128) {
        // ================= producers (warps 4-5) =================
        const int ptid = t - 128;              // 0..63 (= d)
        float xr0[32], xr1[32];
        {
            const float* xp0 = x + (size_t)b0 * 2048 + ptid;
            const float* xp1 = x + (size_t)(b0 + 1) * 2048 + ptid;
#pragma unroll
            for (int m = 0; m < 32; m++) { xr0[m] = xp0[m * 64]; xr1[m] = xp1[m * 64]; }
        }
        const float* hp0 = hbas + (size_t)b0 * 8192 + ptid;
        const float* hp1 = hbas + (size_t)(b0 + 1) * 8192 + ptid;

        int ps = 0; uint32_t pph = 1;
        for (int c = 0; c < NC; c++) {
            mbar_wait(sb + 16 * ps + 8, pph);   // stage free
            const int s = ps;
            if (++ps == 3) { ps = 0; pph ^= 1u; }
            const uint32_t stg = stg0 + (uint32_t)s * 32768u;
            // B: this CTA's 128 h rows = 1024 x 16B chunks over 64 threads -> 16 cp16.
            const __half* ws = wt + (size_t)c * 16384 + (size_t)hseg * 64;
#pragma unroll
            for (int i = 0; i < 16; i++) {
                const int p = ptid + i * 64;
                const int h = p >> 3, j = p & 7;
                cp16(stg + 16384u + (uint32_t)h * 128u + (uint32_t)((j ^ (h & 7)) << 4),
                     ws + (size_t)h * 64 + j * 8);
            }
            cp_mbar_arrive(sb + 16 * s);
            // A: rows ptid (batch b0) and ptid+64 (batch b0+1).
            if (L == 0) {
                // folded pairs: A[row][kk] = x[m]*x[n], p = 64c+kk.
                int m0 = 0;
                while (tribase(m0 + 1) <= 64 * c) ++m0;
                const int n0 = m0 + (64 * c - tribase(m0));
#pragma unroll
                for (int r2 = 0; r2 < 2; r2++) {
                    const int row = ptid + r2 * 64;
                    const float* xr = r2 ? xr1 : xr0;
                    const uint32_t asw = (uint32_t)(row & 7);
                    char* ab = smb + (stg - sb) + (uint32_t)row * 128u;
                    int m = m0, n = n0;
#pragma unroll
                    for (int j = 0; j < 8; j++) {
                        float f[8];
#pragma unroll
                        for (int q = 0; q < 8; q++) {
                            if (64 * c + 8 * j + q < 528) {
                                f[q] = xr[m] * xr[n];
                                if (++n == 32) { ++m; n = m; }
                            } else f[q] = 0.0f;
                        }
                        uint4 v;
                        v.x = h2u(__floats2half2_rn(f[0], f[1]));
                        v.y = h2u(__floats2half2_rn(f[2], f[3]));
                        v.z = h2u(__floats2half2_rn(f[4], f[5]));
                        v.w = h2u(__floats2half2_rn(f[6], f[7]));
                        *reinterpret_cast<uint4*>(ab + ((((uint32_t)j) ^ asw) << 4)) = v;
                    }
                }
            } else {
#pragma unroll
                for (int r2 = 0; r2 < 2; r2++) {
                    const int row = ptid + r2 * 64;
                    const float* xr = r2 ? xr1 : xr0;
                    const float* hp = r2 ? hp1 : hp0;
                    const uint32_t asw = (uint32_t)(row & 7);
                    char* ab = smb + (stg - sb) + (uint32_t)row * 128u;
#pragma unroll
                    for (int nl = 0; nl < 2; nl++) {
                        const float hv = hp[(size_t)(2 * c + nl) * 64];
#pragma unroll
                        for (int u = 0; u < 4; u++) {
                            uint4 v;
                            v.x = h2u(__floats2half2_rn(xr[8*u+0]*hv, xr[8*u+1]*hv));
                            v.y = h2u(__floats2half2_rn(xr[8*u+2]*hv, xr[8*u+3]*hv));
                            v.z = h2u(__floats2half2_rn(xr[8*u+4]*hv, xr[8*u+5]*hv));
                            v.w = h2u(__floats2half2_rn(xr[8*u+6]*hv, xr[8*u+7]*hv));
                            const int j = nl * 4 + u;
                            *reinterpret_cast<uint4*>(ab + ((((uint32_t)j) ^ asw) << 4)) = v;
                        }
                    }
                }
            }
            mbar_arrive(sb + 16 * s);           // A ready (release)
        }
        return;
    }

    // ================= consumers (warps 0-3) =================
    const int mg = wid >> 1, ng = wid & 1;      // 2x2 grid of 64x64 tiles
    const int arow = mg * 64 + (lane & 15);
    const int brow = ng * 64 + ((lane >> 4) << 3) + (lane & 7);
    const uint32_t axor = (uint32_t)(arow & 7);
    const uint32_t bxor = (uint32_t)(brow & 7);
    const uint32_t aof = (uint32_t)arow * 128u;
    const uint32_t bof = 16384u + (uint32_t)brow * 128u;
    const uint32_t acs = (uint32_t)(lane >> 4);
    const uint32_t bcs = (uint32_t)((lane >> 3) & 1);

    float acc[4][8][4];
#pragma unroll
    for (int i = 0; i < 4; i++)
#pragma unroll
        for (int j = 0; j < 8; j++)
#pragma unroll
            for (int q = 0; q < 4; q++) acc[i][j][q] = 0.0f;

    int cs = 0; uint32_t cph = 0;
    for (int c = 0; c < NC; c++) {
        mbar_wait(sb + 16 * cs, cph);           // stage full
        const int s = cs;
        if (++cs == 3) { cs = 0; cph ^= 1u; }
        const uint32_t stg = stg0 + (uint32_t)s * 32768u;
#pragma unroll
        for (int ks = 0; ks < 4; ks++) {
            uint32_t af[4][4], bf[4][4];
#pragma unroll
            for (int mt = 0; mt < 4; mt++)
                ldsm4(af[mt], stg + aof + (uint32_t)(mt * 16 * 128) +
                              ((((uint32_t)(2 * ks) + acs) ^ axor) << 4));
#pragma unroll
            for (int np = 0; np < 4; np++)
                ldsm4(bf[np], stg + bof + (uint32_t)(np * 16 * 128) +
                              ((((uint32_t)(2 * ks) + bcs) ^ bxor) << 4));
#pragma unroll
            for (int mt = 0; mt < 4; mt++)
#pragma unroll
                for (int nt = 0; nt < 8; nt++)
                    mma16(acc[mt][nt], af[mt], &bf[nt >> 1][(nt & 1) * 2]);
        }
        mbar_arrive(sb + 16 * s + 8);           // stage consumed
    }

    // ---- epilogue: bias+relu. h-global = hseg + local.
    //      L<2, hseg==0  -> fused fc dot; L<2, hseg==128 -> g_h write; L==2 -> fc dot. ----
    const int b = b0 + mg;
    const int dq = lane >> 2, hq = (lane & 3) * 2;
    if (L == 2 || hseg == 0) {
        const int fcoff = (L == 0) ? 0 : (L == 1) ? 128 : 256 + hseg;
        float p = 0.0f;
#pragma unroll
        for (int nt = 0; nt < 8; nt++) {
            const int hl = ng * 64 + nt * 8 + hq;
            const float bv0 = __ldg(bias + hseg + hl), bv1 = __ldg(bias + hseg + hl + 1);
            const float w0 = __ldg(fcW + fcoff + hl), w1 = __ldg(fcW + fcoff + hl + 1);
            float s0 = 0.0f, s1 = 0.0f;
#pragma unroll
            for (int mt = 0; mt < 4; mt++) {
                s0 += fmaxf(acc[mt][nt][0] + bv0, 0.f) + fmaxf(acc[mt][nt][2] + bv0, 0.f);
                s1 += fmaxf(acc[mt][nt][1] + bv1, 0.f) + fmaxf(acc[mt][nt][3] + bv1, 0.f);
            }
            p += s0 * w0 + s1 * w1;
        }
#pragma unroll
        for (int o = 16; o > 0; o >>= 1) p += __shfl_xor_sync(0xFFFFFFFFu, p, o);
        if (lane == 0) atomicAdd(out + b, p);
    } else {
        float* yo = (L == 0 ? g_h0 : g_h1) + (size_t)b * 8192;
#pragma unroll
        for (int mt = 0; mt < 4; mt++) {
            const int d = mt * 16 + dq;
#pragma unroll
            for (int nt = 0; nt < 8; nt++) {
                const int hl = ng * 64 + nt * 8 + hq;       // = n (local row of g_h)
                const float bv0 = __ldg(bias + 128 + hl), bv1 = __ldg(bias + 128 + hl + 1);
                yo[(size_t)hl * 64 + d]           = fmaxf(acc[mt][nt][0] + bv0, 0.f);
                yo[(size_t)(hl + 1) * 64 + d]     = fmaxf(acc[mt][nt][1] + bv1, 0.f);
                yo[(size_t)hl * 64 + d + 8]       = fmaxf(acc[mt][nt][2] + bv0, 0.f);
                yo[(size_t)(hl + 1) * 64 + d + 8] = fmaxf(acc[mt][nt][3] + bv1, 0.f);
            }
        }
    }
}

extern "C" void kernel_launch(void* const* d_in, const int* in_sizes, int n_in,
                              void* d_out, int out_size) {
    const float* x   = (const float*)d_in[0];
    const float* W0  = (const float*)d_in[1];
    const float* b0  = (const float*)d_in[2];
    const float* W1  = (const float*)d_in[3];
    const float* b1  = (const float*)d_in[4];
    const float* W2  = (const float*)d_in[5];
    const float* b2  = (const float*)d_in[6];
    const float* fcW = (const float*)d_in[7];
    const float* fcb = (const float*)d_in[8];
    float* out = (float*)d_out;

    // align pad + mbar header + 3 x 32KB stages = 98KB -> 2 CTAs/SM
    constexpr int SMEMSZ = 1024 + 1024 + 3 * 32768;
    cudaFuncSetAttribute(cin_layer<0>, cudaFuncAttributeMaxDynamicSharedMemorySize, SMEMSZ);
    cudaFuncSetAttribute(cin_layer<1>, cudaFuncAttributeMaxDynamicSharedMemorySize, SMEMSZ);
    cudaFuncSetAttribute(cin_layer<2>, cudaFuncAttributeMaxDynamicSharedMemorySize, SMEMSZ);

    __half *wt0p, *wt1p, *wt2p;
    cudaGetSymbolAddress((void**)&wt0p, g_wt0);
    cudaGetSymbolAddress((void**)&wt1p, g_wt1);
    cudaGetSymbolAddress((void**)&wt2p, g_wt2);

    prep<<<141, 256>>>(W0, W1, W2, fcb, out, wt0p, wt1p, wt2p);

    cin_layer<0><<<1024, 192, SMEMSZ>>>(x, b0, fcW, out);
    cin_layer<1><<<1024, 192, SMEMSZ>>>(x, b1, fcW, out);
    cin_layer<2><<<1024, 192, SMEMSZ>>>(x, b2, fcW, out);
}